// round 9
// baseline (speedup 1.0000x reference)
#include <cuda_runtime.h>

// SpatialAwareFocalLoss — GB300 sm_103a, round 9.
// R8 algorithm (grid=128: 2 CTAs/seq × 4 classes; line bins; packed-word
// finish) with 512-thread blocks, 2 tokens/thread: doubles per-warp ILP
// (MLP=8 entry, 2 interleaved MUFU chains), halves barrier width (16 warps).

static constexpr int S    = 1024;   // SEQ_LEN
static constexpr int H    = 512;    // threads per CTA (tokens i, i+H)
static constexpr int NBIN = 262;    // bin idx = line + 2, lines 0..255

__device__ unsigned long long g_word = 0ULL;   // [63:48]=count, [47:0]=sum*2^32

__device__ __forceinline__ float class_math(const float4& p4, const float4& ts,
                                            float& sigsum)
{
    float p[4] = {p4.x, p4.y, p4.z, p4.w};
    float t[4] = {ts.x, ts.y, ts.z, ts.w};
    float local = 0.0f;
    #pragma unroll
    for (int c = 0; c < 4; ++c) {
        const float x = p[c];
        const float e = __expf(-fabsf(x));
        const float a = 1.0f / (1.0f + e);        // sigmoid(|x|)
        const float g = e * a;                    // 1 - sigmoid(|x|)
        const float sig  = (x >= 0.0f) ? a : g;
        const float sig1 = (x >= 0.0f) ? g : a;   // 1 - sig
        sigsum += sig;
        const float pt  = (t[c] > 0.5f) ? sig : sig1;
        const float omp = (t[c] > 0.5f) ? sig1 : sig;   // 1 - pt
        const float bce = -__logf(pt);
        const float o2  = omp * omp;
        local += 0.01f * o2 * o2 * bce;           // ALPHA*(1-pt)^GAMMA*bce
    }
    return local;
}

__global__ __launch_bounds__(H, 1)
void focal_kernel(const float* __restrict__ pred,
                  const float* __restrict__ target,
                  const int*   __restrict__ token_to_line,
                  float* __restrict__ out,
                  float inv_total, int nblocks)
{
    __shared__ int   s_bin_i[NBIN];  // cnt + (tsum<<16)
    __shared__ float s_bin_f[NBIN];  // this half's sigmoid sum per line
    __shared__ float s_red[16];

    const int bid  = blockIdx.x;
    const int b    = bid >> 1;        // sequence
    const int half = bid & 1;         // classes 0-3 or 4-7
    const int i    = threadIdx.x;     // token pair (i, i+H)
    const int lane = i & 31, warp = i >> 5;

    const long tok0 = (long)b * S + i;
    const long tok1 = tok0 + H;
    const long b0   = tok0 * 8;
    const long b1   = tok1 * 8;

    // 8 independent loads issued up front (MLP=8)
    const int    li0 = __ldg(token_to_line + tok0);
    const int    li1 = __ldg(token_to_line + tok1);
    const float4 p40 = __ldg((const float4*)(pred + b0 + half * 4));
    const float4 p41 = __ldg((const float4*)(pred + b1 + half * 4));
    const float4 ta0 = __ldg((const float4*)(target + b0));
    const float4 tb0 = __ldg((const float4*)(target + b0 + 4));
    const float4 ta1 = __ldg((const float4*)(target + b1));
    const float4 tb1 = __ldg((const float4*)(target + b1 + 4));

    if (i < NBIN) { s_bin_i[i] = 0; s_bin_f[i] = 0.0f; }

    // full-class token target sums (small integers, exact) -> window gates
    const int tint0 = (int)(ta0.x + ta0.y + ta0.z + ta0.w +
                            tb0.x + tb0.y + tb0.z + tb0.w);
    const int tint1 = (int)(ta1.x + ta1.y + ta1.z + ta1.w +
                            tb1.x + tb1.y + tb1.z + tb1.w);

    float sig0 = 0.0f, sig1 = 0.0f;
    float local = class_math(p40, half ? tb0 : ta0, sig0)
                + class_math(p41, half ? tb1 : ta1, sig1);

    __syncthreads();                              // barrier 1: bins zeroed

    const int self0 = 1 + (tint0 << 16);
    const int self1 = 1 + (tint1 << 16);
    atomicAdd(&s_bin_i[li0 + 2], self0);
    atomicAdd(&s_bin_f[li0 + 2], sig0);
    atomicAdd(&s_bin_i[li1 + 2], self1);
    atomicAdd(&s_bin_f[li1 + 2], sig1);
    __syncthreads();                              // barrier 2: bins complete

    // window lines [li-2, li+2] -> bins [li, li+4]; exclude self
    int   ci0 = -self0,  ci1 = -self1;
    float ns0 = -sig0,   ns1 = -sig1;
    #pragma unroll
    for (int k = 0; k < 5; ++k) {
        ci0 += s_bin_i[li0 + k];  ns0 += s_bin_f[li0 + k];
        ci1 += s_bin_i[li1 + k];  ns1 += s_bin_f[li1 + k];
    }
    const int cnt0 = ci0 & 0xffff, ntg0 = ci0 >> 16;
    const int cnt1 = ci1 & 0xffff, ntg1 = ci1 >> 16;

    if (cnt0 > 0 && ntg0 > 0) local += 0.03f * __fdividef(ns0, (float)cnt0);
    if (cnt1 > 0 && ntg1 > 0) local += 0.03f * __fdividef(ns1, (float)cnt1);

    // block reduction (16 warps)
    #pragma unroll
    for (int o = 16; o > 0; o >>= 1)
        local += __shfl_xor_sync(0xffffffffu, local, o);
    if (lane == 0) s_red[warp] = local;
    __syncthreads();                              // barrier 3

    if (warp == 0) {
        float v = (lane < 16) ? s_red[lane] : 0.0f;
        #pragma unroll
        for (int o = 8; o > 0; o >>= 1)
            v += __shfl_xor_sync(0xffffffffu, v, o);

        if (lane == 0) {
            // v >= 0 always; fixed-point pack {count<<48 | sum*2^32}
            const unsigned long long fix =
                (unsigned long long)__double2ll_rn((double)v * 4294967296.0);
            const unsigned long long pack = (1ULL << 48) + fix;
            const unsigned long long old  = atomicAdd(&g_word, pack);

            if ((int)(old >> 48) == nblocks - 1) {      // last CTA
                const unsigned long long tot =
                    (old + pack) & ((1ULL << 48) - 1ULL);
                out[0] = (float)((double)tot * (1.0 / 4294967296.0)
                                 * (double)inv_total);
                atomicExch(&g_word, 0ULL);              // reset for next replay
            }
        }
    }
}

extern "C" void kernel_launch(void* const* d_in, const int* in_sizes, int n_in,
                              void* d_out, int out_size)
{
    const float* pred   = (const float*)d_in[0];
    const float* target = (const float*)d_in[1];
    const int*   lines  = (const int*)d_in[2];
    float* out = (float*)d_out;

    const int BS = in_sizes[2];
    const int B  = BS / S;
    const int nblocks = 2 * B;                    // 128 CTAs
    const float inv_total = 1.0f / ((float)BS * 8.0f);

    focal_kernel<<<nblocks, H>>>(pred, target, lines, out, inv_total, nblocks);
}